// round 2
// baseline (speedup 1.0000x reference)
#include <cuda_runtime.h>
#include <cuda_fp16.h>
#include <cstdint>
#include <cstddef>

static constexpr int NT = 2048;   // tokens
static constexpr int NH = 1024;   // hidden
static constexpr int NF = 2816;   // ffn
static constexpr int NE = 8;      // experts

static constexpr int BM = 64;
static constexpr int BN = 64;
static constexpr int BK = 32;
static constexpr int BKP = 40;    // padded row (halves): 80B stride, conflict-free ldmatrix

// ---------------- device scratch (globals: no allocation allowed) ----------------
__device__ int   g_cnt[NE];
__device__ int   g_tok[NE][NT];
__device__ float g_rw[NE][NT];
__device__ __align__(16) __half g_xh[(size_t)NT * NH];                 // 4 MB
__device__ __align__(16) __half g_hbuf[(size_t)NE * NT * NF];          // 92 MB worst case

// ---------------- helpers ----------------
static __device__ __forceinline__ uint32_t smaddr(const void* p) {
    return (uint32_t)__cvta_generic_to_shared(p);
}
static __device__ __forceinline__ void ldm4(uint32_t& r0, uint32_t& r1, uint32_t& r2, uint32_t& r3, uint32_t a) {
    asm volatile("ldmatrix.sync.aligned.m8n8.x4.shared.b16 {%0,%1,%2,%3}, [%4];\n"
                 : "=r"(r0), "=r"(r1), "=r"(r2), "=r"(r3) : "r"(a));
}
static __device__ __forceinline__ void mma16816(float c[4], const uint32_t a[4], const uint32_t b[2]) {
    asm volatile("mma.sync.aligned.m16n8k16.row.col.f32.f16.f16.f32 "
                 "{%0,%1,%2,%3},{%4,%5,%6,%7},{%8,%9},{%0,%1,%2,%3};\n"
                 : "+f"(c[0]), "+f"(c[1]), "+f"(c[2]), "+f"(c[3])
                 : "r"(a[0]), "r"(a[1]), "r"(a[2]), "r"(a[3]), "r"(b[0]), "r"(b[1]));
}

// ---------------- kernels ----------------
__global__ void k_zero() {
    if (threadIdx.x < NE) g_cnt[threadIdx.x] = 0;
}

__global__ void k_convx(const float* __restrict__ x) {
    size_t i = ((size_t)blockIdx.x * blockDim.x + threadIdx.x) * 4;
    float4 v = *(const float4*)(x + i);
    *(__half2*)(g_xh + i)     = __floats2half2_rn(v.x, v.y);
    *(__half2*)(g_xh + i + 2) = __floats2half2_rn(v.z, v.w);
}

// one warp per token: 8 logits, top-2, softmax, append to expert lists
__global__ void k_router(const float* __restrict__ x, const float* __restrict__ gw) {
    int t = blockIdx.x * 8 + (threadIdx.x >> 5);
    int lane = threadIdx.x & 31;
    const float* xr = x + (size_t)t * NH;
    float acc[NE];
#pragma unroll
    for (int e = 0; e < NE; e++) acc[e] = 0.f;
    for (int h = lane; h < NH; h += 32) {
        float xv = xr[h];
#pragma unroll
        for (int e = 0; e < NE; e++) acc[e] += xv * gw[e * NH + h];
    }
#pragma unroll
    for (int e = 0; e < NE; e++)
        for (int o = 16; o > 0; o >>= 1) acc[e] += __shfl_xor_sync(0xffffffffu, acc[e], o);
    if (lane == 0) {
        int i0 = 0; float v0 = acc[0];
#pragma unroll
        for (int e = 1; e < NE; e++) if (acc[e] > v0) { v0 = acc[e]; i0 = e; }
        int i1 = -1; float v1 = -1e30f;
#pragma unroll
        for (int e = 0; e < NE; e++) if (e != i0 && acc[e] > v1) { v1 = acc[e]; i1 = e; }
        float w0 = 1.f / (1.f + expf(v1 - v0));   // softmax over {v0,v1}
        float w1 = 1.f - w0;
        int p0 = atomicAdd(&g_cnt[i0], 1); g_tok[i0][p0] = t; g_rw[i0][p0] = w0;
        int p1 = atomicAdd(&g_cnt[i1], 1); g_tok[i1][p1] = t; g_rw[i1][p1] = w1;
    }
}

// FFN1: for expert e, rows = gathered tokens; compute silu(x w1^T) * (x w3^T) -> g_hbuf (fp16)
__global__ __launch_bounds__(128) void k_ffn1(const float* __restrict__ w1, const float* __restrict__ w3) {
    const int e   = blockIdx.z;
    const int cnt = g_cnt[e];
    const int m0  = blockIdx.y * BM;
    if (m0 >= cnt) return;
    const int n0  = blockIdx.x * BN;

    __shared__ __align__(16) __half As [BM][BKP];
    __shared__ __align__(16) __half B1s[BN][BKP];
    __shared__ __align__(16) __half B3s[BN][BKP];

    const int tid = threadIdx.x;
    const int lane = tid & 31, wid = tid >> 5;
    const int wm = (wid >> 1) * 32, wn = (wid & 1) * 32;

    float accG[2][4][4], accU[2][4][4];
#pragma unroll
    for (int i = 0; i < 2; i++)
#pragma unroll
        for (int j = 0; j < 4; j++)
#pragma unroll
            for (int k = 0; k < 4; k++) { accG[i][j][k] = 0.f; accU[i][j][k] = 0.f; }

    const float* w1e = w1 + (size_t)e * NF * NH;
    const float* w3e = w3 + (size_t)e * NF * NH;

    const __half* asrc[2];
#pragma unroll
    for (int rr = 0; rr < 2; rr++) {
        int g = m0 + (tid >> 2) + rr * 32;
        asrc[rr] = (g < cnt) ? (g_xh + (size_t)g_tok[e][g] * NH) : nullptr;
    }
    const int c8 = (tid & 3) * 8;

    for (int kt = 0; kt < NH / BK; kt++) {
        const int k0 = kt * BK;
#pragma unroll
        for (int rr = 0; rr < 2; rr++) {
            int row = (tid >> 2) + rr * 32;
            float4 v;
            if (asrc[rr]) v = *(const float4*)(asrc[rr] + k0 + c8);
            else          v = make_float4(0.f, 0.f, 0.f, 0.f);
            *(float4*)&As[row][c8] = v;
        }
#pragma unroll
        for (int ii = 0; ii < 4; ii++) {
            int i = tid + ii * 128;
            int row = i >> 3, c4 = (i & 7) * 4;
            float4 f1 = *(const float4*)(w1e + (size_t)(n0 + row) * NH + k0 + c4);
            float4 f3 = *(const float4*)(w3e + (size_t)(n0 + row) * NH + k0 + c4);
            *(__half2*)&B1s[row][c4]     = __floats2half2_rn(f1.x, f1.y);
            *(__half2*)&B1s[row][c4 + 2] = __floats2half2_rn(f1.z, f1.w);
            *(__half2*)&B3s[row][c4]     = __floats2half2_rn(f3.x, f3.y);
            *(__half2*)&B3s[row][c4 + 2] = __floats2half2_rn(f3.z, f3.w);
        }
        __syncthreads();
#pragma unroll
        for (int ks = 0; ks < 2; ks++) {
            uint32_t af[2][4];
#pragma unroll
            for (int mi = 0; mi < 2; mi++) {
                uint32_t a = smaddr(&As[wm + mi * 16 + (lane & 15)][ks * 16 + (lane >> 4) * 8]);
                ldm4(af[mi][0], af[mi][1], af[mi][2], af[mi][3], a);
            }
            uint32_t b1f[4][2], b3f[4][2];
#pragma unroll
            for (int np = 0; np < 2; np++) {
                int j    = lane >> 3;
                int nrow = wn + np * 16 + (j >> 1) * 8 + (lane & 7);
                int kcol = ks * 16 + (j & 1) * 8;
                ldm4(b1f[2 * np][0], b1f[2 * np][1], b1f[2 * np + 1][0], b1f[2 * np + 1][1],
                     smaddr(&B1s[nrow][kcol]));
                ldm4(b3f[2 * np][0], b3f[2 * np][1], b3f[2 * np + 1][0], b3f[2 * np + 1][1],
                     smaddr(&B3s[nrow][kcol]));
            }
#pragma unroll
            for (int mi = 0; mi < 2; mi++)
#pragma unroll
                for (int ni = 0; ni < 4; ni++) {
                    mma16816(accG[mi][ni], af[mi], b1f[ni]);
                    mma16816(accU[mi][ni], af[mi], b3f[ni]);
                }
        }
        __syncthreads();
    }

    // epilogue: h = silu(g) * u  (fp16 scratch; rows >= cnt are written but never consumed)
#pragma unroll
    for (int mi = 0; mi < 2; mi++)
#pragma unroll
        for (int ni = 0; ni < 4; ni++)
#pragma unroll
            for (int p = 0; p < 2; p++) {
                int row = m0 + wm + mi * 16 + (lane >> 2) + p * 8;
                int col = n0 + wn + ni * 8 + (lane & 3) * 2;
                float g0 = accG[mi][ni][2 * p], g1 = accG[mi][ni][2 * p + 1];
                float u0 = accU[mi][ni][2 * p], u1 = accU[mi][ni][2 * p + 1];
                float h0 = g0 / (1.f + __expf(-g0)) * u0;
                float h1 = g1 / (1.f + __expf(-g1)) * u1;
                *(__half2*)&g_hbuf[((size_t)e * NT + row) * NF + col] = __floats2half2_rn(h0, h1);
            }
}

// FFN2: y = h @ w2^T, scaled scatter-add into out
__global__ __launch_bounds__(128) void k_ffn2(const float* __restrict__ w2, float* __restrict__ out) {
    const int e   = blockIdx.z;
    const int cnt = g_cnt[e];
    const int m0  = blockIdx.y * BM;
    if (m0 >= cnt) return;
    const int n0  = blockIdx.x * BN;   // over hidden dim

    __shared__ __align__(16) __half As[BM][BKP];
    __shared__ __align__(16) __half Bs[BN][BKP];

    const int tid = threadIdx.x;
    const int lane = tid & 31, wid = tid >> 5;
    const int wm = (wid >> 1) * 32, wn = (wid & 1) * 32;

    float acc[2][4][4];
#pragma unroll
    for (int i = 0; i < 2; i++)
#pragma unroll
        for (int j = 0; j < 4; j++)
#pragma unroll
            for (int k = 0; k < 4; k++) acc[i][j][k] = 0.f;

    const float*  w2e = w2 + (size_t)e * NH * NF;
    const __half* hb  = g_hbuf + (size_t)e * NT * NF;
    const int c8 = (tid & 3) * 8;

    for (int kt = 0; kt < NF / BK; kt++) {
        const int k0 = kt * BK;
#pragma unroll
        for (int rr = 0; rr < 2; rr++) {
            int row = (tid >> 2) + rr * 32;
            *(float4*)&As[row][c8] = *(const float4*)(hb + (size_t)(m0 + row) * NF + k0 + c8);
        }
#pragma unroll
        for (int ii = 0; ii < 4; ii++) {
            int i = tid + ii * 128;
            int row = i >> 3, c4 = (i & 7) * 4;
            float4 f = *(const float4*)(w2e + (size_t)(n0 + row) * NF + k0 + c4);
            *(__half2*)&Bs[row][c4]     = __floats2half2_rn(f.x, f.y);
            *(__half2*)&Bs[row][c4 + 2] = __floats2half2_rn(f.z, f.w);
        }
        __syncthreads();
#pragma unroll
        for (int ks = 0; ks < 2; ks++) {
            uint32_t af[2][4];
#pragma unroll
            for (int mi = 0; mi < 2; mi++) {
                uint32_t a = smaddr(&As[wm + mi * 16 + (lane & 15)][ks * 16 + (lane >> 4) * 8]);
                ldm4(af[mi][0], af[mi][1], af[mi][2], af[mi][3], a);
            }
            uint32_t bf[4][2];
#pragma unroll
            for (int np = 0; np < 2; np++) {
                int j    = lane >> 3;
                int nrow = wn + np * 16 + (j >> 1) * 8 + (lane & 7);
                int kcol = ks * 16 + (j & 1) * 8;
                ldm4(bf[2 * np][0], bf[2 * np][1], bf[2 * np + 1][0], bf[2 * np + 1][1],
                     smaddr(&Bs[nrow][kcol]));
            }
#pragma unroll
            for (int mi = 0; mi < 2; mi++)
#pragma unroll
                for (int ni = 0; ni < 4; ni++)
                    mma16816(acc[mi][ni], af[mi], bf[ni]);
        }
        __syncthreads();
    }

#pragma unroll
    for (int mi = 0; mi < 2; mi++)
#pragma unroll
        for (int ni = 0; ni < 4; ni++)
#pragma unroll
            for (int p = 0; p < 2; p++) {
                int slot = m0 + wm + mi * 16 + (lane >> 2) + p * 8;
                if (slot < cnt) {
                    int   t  = g_tok[e][slot];
                    float rw = g_rw[e][slot];
                    int col = n0 + wn + ni * 8 + (lane & 3) * 2;
                    atomicAdd(&out[(size_t)t * NH + col],     rw * acc[mi][ni][2 * p]);
                    atomicAdd(&out[(size_t)t * NH + col + 1], rw * acc[mi][ni][2 * p + 1]);
                }
            }
}

// ---------------- launch ----------------
extern "C" void kernel_launch(void* const* d_in, const int* in_sizes, int n_in,
                              void* d_out, int out_size) {
    const float* x  = (const float*)d_in[0];
    const float* gw = (const float*)d_in[1];
    const float* w1 = (const float*)d_in[2];
    const float* w3 = (const float*)d_in[3];
    const float* w2 = (const float*)d_in[4];
    float* out = (float*)d_out;

    cudaMemsetAsync(out, 0, (size_t)NT * NH * sizeof(float));
    k_zero<<<1, 32>>>();
    k_convx<<<(NT * NH / 4) / 256, 256>>>(x);
    k_router<<<NT / 8, 256>>>(x, gw);
    k_ffn1<<<dim3(NF / BN, NT / BM, NE), 128>>>(w1, w3);
    k_ffn2<<<dim3(NH / BN, NT / BM, NE), 128>>>(w2, out);
}

// round 4
// speedup vs baseline: 1.3567x; 1.3567x over previous
#include <cuda_runtime.h>
#include <cuda_fp16.h>
#include <cstdint>
#include <cstddef>

static constexpr int NT = 2048;   // tokens
static constexpr int NH = 1024;   // hidden
static constexpr int NF = 2816;   // ffn
static constexpr int NE = 8;      // experts

static constexpr int BM  = 128;
static constexpr int BN  = 128;
static constexpr int BK  = 32;
static constexpr int BKP = 40;    // padded row stride in halves (80B) -> conflict-free ldmatrix
static constexpr int NTHR = 512;  // 16 warps: 4 (M) x 4 (N), warp tile 32x32

static constexpr int SMEM1 = (2 * BM * BKP + 2 * BN * BKP + 2 * BN * BKP) * 2; // A + B1 + B3, 2 stages
static constexpr int SMEM2 = (2 * BM * BKP + 2 * BN * BKP) * 2;                // A + B

// ---------------- device scratch ----------------
__device__ int   g_cnt[NE];
__device__ int   g_tok[NE][NT];
__device__ float g_rw[NE][NT];
__device__ __align__(16) __half g_xh[(size_t)NT * NH];
__device__ __align__(16) __half g_hbuf[(size_t)NE * NT * NF];

// ---------------- helpers ----------------
static __device__ __forceinline__ uint32_t smaddr(const void* p) {
    return (uint32_t)__cvta_generic_to_shared(p);
}
static __device__ __forceinline__ void ldm4(uint32_t& r0, uint32_t& r1, uint32_t& r2, uint32_t& r3, uint32_t a) {
    asm volatile("ldmatrix.sync.aligned.m8n8.x4.shared.b16 {%0,%1,%2,%3}, [%4];\n"
                 : "=r"(r0), "=r"(r1), "=r"(r2), "=r"(r3) : "r"(a));
}
static __device__ __forceinline__ void mma16816(float c[4], const uint32_t a[4], const uint32_t b[2]) {
    asm volatile("mma.sync.aligned.m16n8k16.row.col.f32.f16.f16.f32 "
                 "{%0,%1,%2,%3},{%4,%5,%6,%7},{%8,%9},{%0,%1,%2,%3};\n"
                 : "+f"(c[0]), "+f"(c[1]), "+f"(c[2]), "+f"(c[3])
                 : "r"(a[0]), "r"(a[1]), "r"(a[2]), "r"(a[3]), "r"(b[0]), "r"(b[1]));
}
static __device__ __forceinline__ void cp16(void* dst, const void* src) {
    asm volatile("cp.async.cg.shared.global [%0], [%1], 16;\n" :: "r"(smaddr(dst)), "l"(src));
}
static __device__ __forceinline__ void cp_commit() { asm volatile("cp.async.commit_group;\n"); }
static __device__ __forceinline__ void cp_wait0()  { asm volatile("cp.async.wait_group 0;\n"); }

// ---------------- small kernels ----------------
__global__ void k_zero() {
    if (threadIdx.x < NE) g_cnt[threadIdx.x] = 0;
}

__global__ void k_convx(const float* __restrict__ x) {
    size_t i = ((size_t)blockIdx.x * blockDim.x + threadIdx.x) * 4;
    float4 v = *(const float4*)(x + i);
    *(__half2*)(g_xh + i)     = __floats2half2_rn(v.x, v.y);
    *(__half2*)(g_xh + i + 2) = __floats2half2_rn(v.z, v.w);
}

__global__ void k_router(const float* __restrict__ x, const float* __restrict__ gw) {
    int t = blockIdx.x * 8 + (threadIdx.x >> 5);
    int lane = threadIdx.x & 31;
    const float* xr = x + (size_t)t * NH;
    float acc[NE];
#pragma unroll
    for (int e = 0; e < NE; e++) acc[e] = 0.f;
    for (int h = lane; h < NH; h += 32) {
        float xv = xr[h];
#pragma unroll
        for (int e = 0; e < NE; e++) acc[e] += xv * gw[e * NH + h];
    }
#pragma unroll
    for (int e = 0; e < NE; e++)
        for (int o = 16; o > 0; o >>= 1) acc[e] += __shfl_xor_sync(0xffffffffu, acc[e], o);
    if (lane == 0) {
        int i0 = 0; float v0 = acc[0];
#pragma unroll
        for (int e = 1; e < NE; e++) if (acc[e] > v0) { v0 = acc[e]; i0 = e; }
        int i1 = -1; float v1 = -1e30f;
#pragma unroll
        for (int e = 0; e < NE; e++) if (e != i0 && acc[e] > v1) { v1 = acc[e]; i1 = e; }
        float w0 = 1.f / (1.f + expf(v1 - v0));
        float w1 = 1.f - w0;
        int p0 = atomicAdd(&g_cnt[i0], 1); g_tok[i0][p0] = t; g_rw[i0][p0] = w0;
        int p1 = atomicAdd(&g_cnt[i1], 1); g_tok[i1][p1] = t; g_rw[i1][p1] = w1;
    }
}

// ---------------- FFN1: h = silu(x w1^T) * (x w3^T) ----------------
__global__ __launch_bounds__(NTHR) void k_ffn1(const float* __restrict__ w1, const float* __restrict__ w3) {
    const int e   = blockIdx.z;
    const int cnt = g_cnt[e];
    const int m0  = blockIdx.y * BM;
    if (m0 >= cnt) return;
    const int n0  = blockIdx.x * BN;

    extern __shared__ __half sm[];
    __half (*As)[BM][BKP]  = (__half(*)[BM][BKP])sm;
    __half (*B1s)[BN][BKP] = (__half(*)[BN][BKP])(sm + 2 * BM * BKP);
    __half (*B3s)[BN][BKP] = (__half(*)[BN][BKP])(sm + 2 * BM * BKP + 2 * BN * BKP);

    const int tid  = threadIdx.x;
    const int lane = tid & 31, wid = tid >> 5;
    const int wm = (wid & 3) * 32, wn = (wid >> 2) * 32;

    const float* w1e = w1 + (size_t)e * NF * NH;
    const float* w3e = w3 + (size_t)e * NF * NH;

    // per-thread A gather source (row fixed; k advances)
    const int arow = tid >> 2;
    const int acol = (tid & 3) * 8;
    int gidx = m0 + arow; if (gidx > cnt - 1) gidx = cnt - 1;
    const __half* a_src = g_xh + (size_t)g_tok[e][gidx] * NH + acol;

    float accG[2][4][4], accU[2][4][4];
#pragma unroll
    for (int i = 0; i < 2; i++)
#pragma unroll
        for (int j = 0; j < 4; j++)
#pragma unroll
            for (int k = 0; k < 4; k++) { accG[i][j][k] = 0.f; accU[i][j][k] = 0.f; }

    const int KT = NH / BK;

    // prologue: tile 0
    {
        float4 pb1[2], pb3[2];
#pragma unroll
        for (int ii = 0; ii < 2; ii++) {
            int i = tid + ii * NTHR; int row = i >> 3, c4 = (i & 7) * 4;
            pb1[ii] = *(const float4*)(w1e + (size_t)(n0 + row) * NH + c4);
            pb3[ii] = *(const float4*)(w3e + (size_t)(n0 + row) * NH + c4);
        }
        cp16(&As[0][arow][acol], a_src);
        cp_commit();
#pragma unroll
        for (int ii = 0; ii < 2; ii++) {
            int i = tid + ii * NTHR; int row = i >> 3, c4 = (i & 7) * 4;
            *(__half2*)&B1s[0][row][c4]     = __floats2half2_rn(pb1[ii].x, pb1[ii].y);
            *(__half2*)&B1s[0][row][c4 + 2] = __floats2half2_rn(pb1[ii].z, pb1[ii].w);
            *(__half2*)&B3s[0][row][c4]     = __floats2half2_rn(pb3[ii].x, pb3[ii].y);
            *(__half2*)&B3s[0][row][c4 + 2] = __floats2half2_rn(pb3[ii].z, pb3[ii].w);
        }
        cp_wait0();
        __syncthreads();
    }

    for (int kt = 0; kt < KT; kt++) {
        const int cur = kt & 1, nxt = cur ^ 1;
        const bool pf = (kt + 1 < KT);
        const int k1 = (kt + 1) * BK;
        float4 pb1[2], pb3[2];
        if (pf) {
#pragma unroll
            for (int ii = 0; ii < 2; ii++) {
                int i = tid + ii * NTHR; int row = i >> 3, c4 = (i & 7) * 4;
                pb1[ii] = *(const float4*)(w1e + (size_t)(n0 + row) * NH + k1 + c4);
                pb3[ii] = *(const float4*)(w3e + (size_t)(n0 + row) * NH + k1 + c4);
            }
            cp16(&As[nxt][arow][acol], a_src + k1);
            cp_commit();
        }

#pragma unroll
        for (int ks = 0; ks < 2; ks++) {
            uint32_t af[2][4];
#pragma unroll
            for (int mi = 0; mi < 2; mi++) {
                uint32_t a = smaddr(&As[cur][wm + mi * 16 + (lane & 15)][ks * 16 + (lane >> 4) * 8]);
                ldm4(af[mi][0], af[mi][1], af[mi][2], af[mi][3], a);
            }
            uint32_t b1f[4][2], b3f[4][2];
#pragma unroll
            for (int np = 0; np < 2; np++) {
                int j    = lane >> 3;
                int nrow = wn + np * 16 + (j >> 1) * 8 + (lane & 7);
                int kcol = ks * 16 + (j & 1) * 8;
                ldm4(b1f[2 * np][0], b1f[2 * np][1], b1f[2 * np + 1][0], b1f[2 * np + 1][1],
                     smaddr(&B1s[cur][nrow][kcol]));
                ldm4(b3f[2 * np][0], b3f[2 * np][1], b3f[2 * np + 1][0], b3f[2 * np + 1][1],
                     smaddr(&B3s[cur][nrow][kcol]));
            }
#pragma unroll
            for (int mi = 0; mi < 2; mi++)
#pragma unroll
                for (int ni = 0; ni < 4; ni++) {
                    mma16816(accG[mi][ni], af[mi], b1f[ni]);
                    mma16816(accU[mi][ni], af[mi], b3f[ni]);
                }
        }

        if (pf) {
#pragma unroll
            for (int ii = 0; ii < 2; ii++) {
                int i = tid + ii * NTHR; int row = i >> 3, c4 = (i & 7) * 4;
                *(__half2*)&B1s[nxt][row][c4]     = __floats2half2_rn(pb1[ii].x, pb1[ii].y);
                *(__half2*)&B1s[nxt][row][c4 + 2] = __floats2half2_rn(pb1[ii].z, pb1[ii].w);
                *(__half2*)&B3s[nxt][row][c4]     = __floats2half2_rn(pb3[ii].x, pb3[ii].y);
                *(__half2*)&B3s[nxt][row][c4 + 2] = __floats2half2_rn(pb3[ii].z, pb3[ii].w);
            }
            cp_wait0();
            __syncthreads();
        }
    }

    // epilogue: h = silu(g)*u -> fp16 scratch (pad rows written but never consumed)
#pragma unroll
    for (int mi = 0; mi < 2; mi++)
#pragma unroll
        for (int ni = 0; ni < 4; ni++)
#pragma unroll
            for (int p = 0; p < 2; p++) {
                int row = m0 + wm + mi * 16 + (lane >> 2) + p * 8;
                int col = n0 + wn + ni * 8 + (lane & 3) * 2;
                float g0 = accG[mi][ni][2 * p], g1 = accG[mi][ni][2 * p + 1];
                float u0 = accU[mi][ni][2 * p], u1 = accU[mi][ni][2 * p + 1];
                float h0 = g0 / (1.f + __expf(-g0)) * u0;
                float h1 = g1 / (1.f + __expf(-g1)) * u1;
                *(__half2*)&g_hbuf[((size_t)e * NT + row) * NF + col] = __floats2half2_rn(h0, h1);
            }
}

// ---------------- FFN2: y = h w2^T, scaled scatter-add ----------------
__global__ __launch_bounds__(NTHR) void k_ffn2(const float* __restrict__ w2, float* __restrict__ out) {
    const int e   = blockIdx.z;
    const int cnt = g_cnt[e];
    const int m0  = blockIdx.y * BM;
    if (m0 >= cnt) return;
    const int n0  = blockIdx.x * BN;

    extern __shared__ __half sm[];
    __half (*As)[BM][BKP] = (__half(*)[BM][BKP])sm;
    __half (*Bs)[BN][BKP] = (__half(*)[BN][BKP])(sm + 2 * BM * BKP);

    const int tid  = threadIdx.x;
    const int lane = tid & 31, wid = tid >> 5;
    const int wm = (wid & 3) * 32, wn = (wid >> 2) * 32;

    const float*  w2e = w2 + (size_t)e * NH * NF;
    const __half* hb  = g_hbuf + (size_t)e * NT * NF;

    const int arow = tid >> 2;
    const int acol = (tid & 3) * 8;
    const __half* a_src = hb + (size_t)(m0 + arow) * NF + acol;

    float acc[2][4][4];
#pragma unroll
    for (int i = 0; i < 2; i++)
#pragma unroll
        for (int j = 0; j < 4; j++)
#pragma unroll
            for (int k = 0; k < 4; k++) acc[i][j][k] = 0.f;

    const int KT = NF / BK;

    {
        float4 pb[2];
#pragma unroll
        for (int ii = 0; ii < 2; ii++) {
            int i = tid + ii * NTHR; int row = i >> 3, c4 = (i & 7) * 4;
            pb[ii] = *(const float4*)(w2e + (size_t)(n0 + row) * NF + c4);
        }
        cp16(&As[0][arow][acol], a_src);
        cp_commit();
#pragma unroll
        for (int ii = 0; ii < 2; ii++) {
            int i = tid + ii * NTHR; int row = i >> 3, c4 = (i & 7) * 4;
            *(__half2*)&Bs[0][row][c4]     = __floats2half2_rn(pb[ii].x, pb[ii].y);
            *(__half2*)&Bs[0][row][c4 + 2] = __floats2half2_rn(pb[ii].z, pb[ii].w);
        }
        cp_wait0();
        __syncthreads();
    }

    for (int kt = 0; kt < KT; kt++) {
        const int cur = kt & 1, nxt = cur ^ 1;
        const bool pf = (kt + 1 < KT);
        const int k1 = (kt + 1) * BK;
        float4 pb[2];
        if (pf) {
#pragma unroll
            for (int ii = 0; ii < 2; ii++) {
                int i = tid + ii * NTHR; int row = i >> 3, c4 = (i & 7) * 4;
                pb[ii] = *(const float4*)(w2e + (size_t)(n0 + row) * NF + k1 + c4);
            }
            cp16(&As[nxt][arow][acol], a_src + k1);
            cp_commit();
        }

#pragma unroll
        for (int ks = 0; ks < 2; ks++) {
            uint32_t af[2][4];
#pragma unroll
            for (int mi = 0; mi < 2; mi++) {
                uint32_t a = smaddr(&As[cur][wm + mi * 16 + (lane & 15)][ks * 16 + (lane >> 4) * 8]);
                ldm4(af[mi][0], af[mi][1], af[mi][2], af[mi][3], a);
            }
            uint32_t bf[4][2];
#pragma unroll
            for (int np = 0; np < 2; np++) {
                int j    = lane >> 3;
                int nrow = wn + np * 16 + (j >> 1) * 8 + (lane & 7);
                int kcol = ks * 16 + (j & 1) * 8;
                ldm4(bf[2 * np][0], bf[2 * np][1], bf[2 * np + 1][0], bf[2 * np + 1][1],
                     smaddr(&Bs[cur][nrow][kcol]));
            }
#pragma unroll
            for (int mi = 0; mi < 2; mi++)
#pragma unroll
                for (int ni = 0; ni < 4; ni++)
                    mma16816(acc[mi][ni], af[mi], bf[ni]);
        }

        if (pf) {
#pragma unroll
            for (int ii = 0; ii < 2; ii++) {
                int i = tid + ii * NTHR; int row = i >> 3, c4 = (i & 7) * 4;
                *(__half2*)&Bs[nxt][row][c4]     = __floats2half2_rn(pb[ii].x, pb[ii].y);
                *(__half2*)&Bs[nxt][row][c4 + 2] = __floats2half2_rn(pb[ii].z, pb[ii].w);
            }
            cp_wait0();
            __syncthreads();
        }
    }

#pragma unroll
    for (int mi = 0; mi < 2; mi++)
#pragma unroll
        for (int ni = 0; ni < 4; ni++)
#pragma unroll
            for (int p = 0; p < 2; p++) {
                int slot = m0 + wm + mi * 16 + (lane >> 2) + p * 8;
                if (slot < cnt) {
                    int   t  = g_tok[e][slot];
                    float rw = g_rw[e][slot];
                    int col = n0 + wn + ni * 8 + (lane & 3) * 2;
                    atomicAdd(&out[(size_t)t * NH + col],     rw * acc[mi][ni][2 * p]);
                    atomicAdd(&out[(size_t)t * NH + col + 1], rw * acc[mi][ni][2 * p + 1]);
                }
            }
}

// ---------------- launch ----------------
extern "C" void kernel_launch(void* const* d_in, const int* in_sizes, int n_in,
                              void* d_out, int out_size) {
    const float* x  = (const float*)d_in[0];
    const float* gw = (const float*)d_in[1];
    const float* w1 = (const float*)d_in[2];
    const float* w3 = (const float*)d_in[3];
    const float* w2 = (const float*)d_in[4];
    float* out = (float*)d_out;

    static bool attr_done = false;
    if (!attr_done) {
        cudaFuncSetAttribute(k_ffn1, cudaFuncAttributeMaxDynamicSharedMemorySize, SMEM1);
        cudaFuncSetAttribute(k_ffn2, cudaFuncAttributeMaxDynamicSharedMemorySize, SMEM2);
        attr_done = true;
    }

    cudaMemsetAsync(out, 0, (size_t)NT * NH * sizeof(float));
    k_zero<<<1, 32>>>();
    k_convx<<<(NT * NH / 4) / 256, 256>>>(x);
    k_router<<<NT / 8, 256>>>(x, gw);
    k_ffn1<<<dim3(NF / BN, NT / BM, NE), NTHR, SMEM1>>>(w1, w3);
    k_ffn2<<<dim3(NH / BN, NT / BM, NE), NTHR, SMEM2>>>(w2, out);
}